// round 11
// baseline (speedup 1.0000x reference)
#include <cuda_runtime.h>
#include <cstdint>

// Problem dims (fixed by the dataset)
#define N_  64
#define C_  256
#define T_  64
#define V_  50
#define H_  16
#define P_  10
#define TV  (T_ * V_)          // 3200 floats per (n,c) slab

// output column j -> input column v (concat order of PARTS)
__constant__ int c_cmap[V_] = {
    0,1,2,3,20,
    8,9,10,11,23,24,
    16,17,18,19,
    4,5,6,7,21,22,
    12,13,14,15,
    25,26,27,28,45,
    33,34,35,36,48,49,
    41,42,43,44,
    29,30,31,32,46,47,
    37,38,39,40
};
// output column j -> partition
__constant__ int c_pmap[V_] = {
    0,0,0,0,0,
    1,1,1,1,1,1,
    2,2,2,2,
    3,3,3,3,3,3,
    4,4,4,4,
    5,5,5,5,5,
    6,6,6,6,6,6,
    7,7,7,7,
    8,8,8,8,8,8,
    9,9,9,9
};
// partition -> member input columns (padded to 6) and sizes
__constant__ int c_pvs[P_ * 6] = {
    0,1,2,3,20,0,
    8,9,10,11,23,24,
    16,17,18,19,0,0,
    4,5,6,7,21,22,
    12,13,14,15,0,0,
    25,26,27,28,45,0,
    33,34,35,36,48,49,
    41,42,43,44,0,0,
    29,30,31,32,46,47,
    37,38,39,40,0,0
};
__constant__ int c_psize[P_] = {5,6,4,6,4,5,6,4,6,4};

// Scratch (alloc-free rule: __device__ globals).
__device__ float    g_avg [N_ * P_ * C_];    // [n][p][c]
__device__ float    g_max [N_ * P_ * C_];
__device__ float    g_h   [N_ * P_ * H_];    // [n][p][i]
__device__ unsigned g_cnt [N_];              // monotonic tickets (replay-safe)
__device__ unsigned g_hcnt[N_];              // monotonic h-ready counters

// ---------------------------------------------------------------------------
// Fused kernel: one block per (n,c) slab. x touches LTS/DRAM exactly once.
//   1. stage slab GMEM -> smem (float4), column-reduce, per-part avg/max
//   2. publish partials; take monotonic ticket; last block of batch computes
//      h[n] (the shared MLP hidden layer) and releases hcnt[n]
//   3. all blocks spin for hcnt[n] >= run+1, compute own 10 gates, scale
//      the smem-resident slab into out (coalesced streaming stores)
// ---------------------------------------------------------------------------
__global__ __launch_bounds__(256)
void fused_kernel(const float4* __restrict__ x4,
                  const float* __restrict__ W1, const float* __restrict__ b1,
                  const float* __restrict__ W2, const float* __restrict__ b2,
                  float* __restrict__ out)
{
    __shared__ float4   sh4[TV / 4];        // 12.8 KB slab
    __shared__ float    ps[200], pm[200];
    __shared__ float    cs[V_ + 2], cmx[V_ + 2];
    __shared__ float    hsm[P_ * H_];       // 160
    __shared__ float    gch[P_ + 2];        // this channel's 10 gates
    __shared__ float2   tab[V_ + 2];
    __shared__ unsigned s_ticket;
    float* sh = (float*)sh4;

    const int nc  = blockIdx.x;
    const int tid = threadIdx.x;
    const int n   = nc >> 8;                // C_ = 256
    const int c   = nc & 255;

    // ---- Phase 1: stage slab + reduce --------------------------------------
    const float4* xb = x4 + (size_t)nc * (TV / 4);
#pragma unroll
    for (int k = 0; k < 3; ++k)
        sh4[tid + 256 * k] = xb[tid + 256 * k];
    if (tid < 32)
        sh4[tid + 768] = xb[tid + 768];
    __syncthreads();

    if (tid < 200) {                        // 50 cols x 4 row-groups of 16
        const int col = tid % V_;
        const int r0  = (tid / V_) * 16;
        float s = 0.f, m = -3.402823466e+38f;
#pragma unroll
        for (int rr = 0; rr < 16; ++rr) {
            const float v = sh[(r0 + rr) * V_ + col];
            s += v;
            m = fmaxf(m, v);
        }
        ps[tid] = s;
        pm[tid] = m;
    }
    __syncthreads();
    if (tid < V_) {
        cs[tid]  = ps[tid] + ps[tid + 50] + ps[tid + 100] + ps[tid + 150];
        cmx[tid] = fmaxf(fmaxf(pm[tid], pm[tid + 50]),
                         fmaxf(pm[tid + 100], pm[tid + 150]));
    }
    __syncthreads();
    if (tid < P_) {
        const int sz = c_psize[tid];
        float s3 = 0.f, m3 = -3.402823466e+38f;
        for (int j = 0; j < sz; ++j) {
            const int vv = c_pvs[tid * 6 + j];
            s3 += cs[vv];
            m3 = fmaxf(m3, cmx[vv]);
        }
        const size_t o = ((size_t)n * P_ + tid) * C_ + c;
        g_avg[o] = s3 / (float)(T_ * sz);
        g_max[o] = m3;
    }

    // ---- Phase 2: ticket; last block of batch computes h -------------------
    __threadfence();                        // release partials
    if (tid == 0)
        s_ticket = atomicAdd(&g_cnt[n], 1u);
    __syncthreads();
    const unsigned ticket = s_ticket;
    const unsigned run    = ticket >> 8;    // graph-replay index (monotonic)

    if ((ticket & 255u) == 255u) {
        // last block of batch n this run: all 256 partial sets are published
        __threadfence();                    // acquire
        const int w = tid >> 5, l = tid & 31;
#pragma unroll
        for (int p = 0; p < P_; ++p) {
#pragma unroll
            for (int ii = 0; ii < 2; ++ii) {
                const int i = w + 8 * ii;
                const float* w1 = W1 + ((size_t)p * H_ + i) * C_;
                const float* av = g_avg + ((size_t)n * P_ + p) * C_;
                const float* mx = g_max + ((size_t)n * P_ + p) * C_;
                float da = 0.f, dm = 0.f;
#pragma unroll
                for (int k = 0; k < 8; ++k) {
                    const int cc = l + 32 * k;
                    const float wv = w1[cc];
                    da += wv * av[cc];
                    dm += wv * mx[cc];
                }
#pragma unroll
                for (int off = 16; off > 0; off >>= 1) {
                    da += __shfl_down_sync(0xffffffffu, da, off);
                    dm += __shfl_down_sync(0xffffffffu, dm, off);
                }
                if (l == 0) {
                    const float bb = b1[p * H_ + i];
                    g_h[((size_t)n * P_ + p) * H_ + i] =
                        fmaxf(da + bb, 0.f) + fmaxf(dm + bb, 0.f);
                }
            }
        }
        __threadfence();                    // release h
        __syncthreads();
        if (tid == 0)
            atomicAdd(&g_hcnt[n], 1u);
    }

    // ---- Phase 3: wait for h, compute gates, scale from smem --------------
    if (tid == 0) {
        while (*(volatile unsigned*)&g_hcnt[n] < run + 1u)
            __nanosleep(64);
    }
    __syncthreads();
    __threadfence();                        // acquire h (run-invariant data)

    if (tid < P_ * H_)
        hsm[tid] = g_h[(size_t)n * P_ * H_ + tid];
    __syncthreads();

    if (tid < P_) {
        const int p = tid;
        const float* w2 = W2 + ((size_t)p * C_ + c) * H_;
        float acc = 2.f * b2[p * C_ + c];
#pragma unroll
        for (int i = 0; i < H_; ++i)
            acc += w2[i] * hsm[p * H_ + i];
        gch[p] = 1.f / (1.f + __expf(-acc));
    }
    __syncthreads();
    if (tid < V_) {
        float2 t;
        t.x = gch[c_pmap[tid]];
        t.y = __int_as_float(c_cmap[tid] - tid);
        tab[tid] = t;
    }
    __syncthreads();

    float* ob = out + (size_t)nc * TV;
    int col = tid % V_;                     // output column of element tid
#pragma unroll
    for (int m = 0; m < 13; ++m) {
        if (m < 12 || tid < 128) {
            const int jj = tid + 256 * m;
            const float2 t = tab[col];
            __stcs(&ob[jj], sh[jj + __float_as_int(t.y)] * t.x);
        }
        col += 6;                           // 256 mod 50
        if (col >= V_) col -= V_;
    }
}

// ---------------------------------------------------------------------------
extern "C" void kernel_launch(void* const* d_in, const int* in_sizes, int n_in,
                              void* d_out, int out_size)
{
    const float* x  = (const float*)d_in[0];
    const float* W1 = (const float*)d_in[1];
    const float* b1 = (const float*)d_in[2];
    const float* W2 = (const float*)d_in[3];
    const float* b2 = (const float*)d_in[4];

    fused_kernel<<<N_ * C_, 256>>>((const float4*)x, W1, b1, W2, b2,
                                   (float*)d_out);
}